// round 12
// baseline (speedup 1.0000x reference)
#include <cuda_runtime.h>
#include <cuda_fp16.h>
#include <cstdint>

#define BN_EPS 1e-5f

// ======================= device scratch (no allocs allowed) =================
static __device__ __half g_xh[1024 * 256];                // x hi, K padded to 256
static __device__ __half g_xl[1024 * 256];                // x lo
static __device__ __half g_w0th[2048 * 256];              // W0^T hi [2048][256]
static __device__ __half g_w0tl[2048 * 256];              // W0^T lo
static __device__ __half g_hh[1024 * 2048];               // trunk hidden hi
static __device__ __half g_hl[1024 * 2048];               // trunk hidden lo
static __device__ __half g_w1th[1024 * 2048];             // W1^T hi [1024][2048]
static __device__ __half g_w1tl[1024 * 2048];             // W1^T lo
static __device__ __half g_fh[1024 * 1024];               // feats fp16
static __device__ __half g_hw1t[128u * 512u * 1024u];     // HW1^T [n][512][1024]
static __device__ __half g_hw2t[128u * 256u * 512u];      // HW2^T [n][256][512]
static __device__ __half g_zh[128u * 1024u * 512u];       // z fp16 [n][1024][512]
static __device__ float g_a0[2048], g_bb0[2048];
static __device__ float g_a1[1024], g_bb1[1024];

// ======================= small helpers ======================================
__device__ __forceinline__ uint32_t smem_to_u32(const void* p) {
    uint32_t a;
    asm("{ .reg .u64 t; cvta.to.shared.u64 t, %1; cvt.u32.u64 %0, t; }" : "=r"(a) : "l"(p));
    return a;
}
__device__ __forceinline__ uint32_t swz128(uint32_t off) {
    return off ^ ((off >> 3) & 0x70);
}
__device__ __forceinline__ void cp_async16(uint32_t dst, const void* src) {
    asm volatile("cp.async.cg.shared.global [%0], [%1], 16;" :: "r"(dst), "l"(src));
}
#define CP_COMMIT() asm volatile("cp.async.commit_group;" ::: "memory")
#define CP_WAIT(n)  asm volatile("cp.async.wait_group %0;" :: "n"(n) : "memory")

#define LDMX4(r, addr) \
    asm volatile("ldmatrix.sync.aligned.m8n8.x4.shared.b16 {%0,%1,%2,%3}, [%4];" \
        : "=r"((r)[0]), "=r"((r)[1]), "=r"((r)[2]), "=r"((r)[3]) : "r"(addr))

#define MMA_F16(d, a, b0_, b1_) \
    asm volatile("mma.sync.aligned.m16n8k16.row.col.f32.f16.f16.f32 " \
        "{%0,%1,%2,%3}, {%4,%5,%6,%7}, {%8,%9}, {%0,%1,%2,%3};" \
        : "+f"((d)[0]), "+f"((d)[1]), "+f"((d)[2]), "+f"((d)[3]) \
        : "r"((a)[0]), "r"((a)[1]), "r"((a)[2]), "r"((a)[3]), "r"(b0_), "r"(b1_))

__device__ __forceinline__ uint32_t pack_h2(__half lo16, __half hi16) {
    return ((uint32_t)__half_as_ushort(hi16) << 16) | __half_as_ushort(lo16);
}

// ================= fused prep: BN fold + converts + transposes ==============
__device__ __forceinline__ void tp64(const float* __restrict__ in,
                                     __half* __restrict__ oh, __half* __restrict__ ol,
                                     int R, int C, int Rpad, int r0, int c0,
                                     float* t, int tid) {
#pragma unroll
    for (int k = 0; k < 4; k++) {
        const int u = tid + k * 256;
        const int r = u >> 4;
        const int cq = (u & 15) * 4;
        const int gr = r0 + r;
        float4 v = make_float4(0.f, 0.f, 0.f, 0.f);
        if (gr < R) v = *(const float4*)(in + (long long)gr * C + c0 + cq);
        t[r * 65 + cq]     = v.x;
        t[r * 65 + cq + 1] = v.y;
        t[r * 65 + cq + 2] = v.z;
        t[r * 65 + cq + 3] = v.w;
    }
    __syncthreads();
#pragma unroll
    for (int k = 0; k < 2; k++) {
        const int u = tid + k * 256;
        const int cc = u >> 3;            // output row (source column) 0..63
        const int r8 = (u & 7) * 8;       // 8 consecutive output cols
        uint32_t hp[4], lp[4];
#pragma unroll
        for (int j = 0; j < 4; j++) {
            const float v0 = t[(r8 + 2 * j) * 65 + cc];
            const float v1 = t[(r8 + 2 * j + 1) * 65 + cc];
            const __half h0 = __float2half(v0), h1 = __float2half(v1);
            hp[j] = pack_h2(h0, h1);
            if (ol) lp[j] = pack_h2(__float2half(v0 - __half2float(h0)),
                                    __float2half(v1 - __half2float(h1)));
        }
        const long long o = (long long)(c0 + cc) * Rpad + r0 + r8;
        *(uint4*)(oh + o) = make_uint4(hp[0], hp[1], hp[2], hp[3]);
        if (ol) *(uint4*)(ol + o) = make_uint4(lp[0], lp[1], lp[2], lp[3]);
    }
}

// segments: bnfold 8 | xconv 512 | W0T 128 | W1T 512 | HW1T 16384 | HW2T 4096
__global__ __launch_bounds__(256)
void prep_all_kernel(const float* __restrict__ x,
                     const float* __restrict__ W0, const float* __restrict__ W1,
                     const float* __restrict__ HW1, const float* __restrict__ HW2,
                     const float* __restrict__ b0, const float* __restrict__ g0,
                     const float* __restrict__ be0, const float* __restrict__ m0,
                     const float* __restrict__ v0,
                     const float* __restrict__ b1, const float* __restrict__ g1,
                     const float* __restrict__ be1, const float* __restrict__ m1,
                     const float* __restrict__ v1) {
    __shared__ float t[64 * 65];
    const int tid = threadIdx.x;
    const int b = blockIdx.x;

    if (b < 8) {
        const int i = b * 256 + tid;
        if (i < 2048) {
            float a = g0[i] / sqrtf(v0[i] + BN_EPS);
            g_a0[i]  = a;
            g_bb0[i] = be0[i] + (b0[i] - m0[i]) * a;
        }
        if (i < 1024) {
            float a = g1[i] / sqrtf(v1[i] + BN_EPS);
            g_a1[i]  = a;
            g_bb1[i] = be1[i] + (b1[i] - m1[i]) * a;
        }
    } else if (b < 520) {
        const int u = (b - 8) * 256 + tid;
        const int row = u >> 7;
        const int c2 = (u & 127) * 2;
        float v0 = (c2     < 200) ? x[row * 200 + c2]     : 0.f;
        float v1 = (c2 + 1 < 200) ? x[row * 200 + c2 + 1] : 0.f;
        __half h0 = __float2half(v0), h1 = __float2half(v1);
        *(uint32_t*)(g_xh + row * 256 + c2) = pack_h2(h0, h1);
        *(uint32_t*)(g_xl + row * 256 + c2) =
            pack_h2(__float2half(v0 - __half2float(h0)),
                    __float2half(v1 - __half2float(h1)));
    } else if (b < 648) {
        const int i = b - 520;
        const int by = i >> 5, bx = i & 31;
        tp64(W0, g_w0th, g_w0tl, 200, 2048, 256, by * 64, bx * 64, t, tid);
    } else if (b < 1160) {
        const int i = b - 648;
        const int by = i >> 4, bx = i & 15;
        tp64(W1, g_w1th, g_w1tl, 2048, 1024, 2048, by * 64, bx * 64, t, tid);
    } else if (b < 17544) {
        const int i = b - 1160;
        const int head = i >> 7;
        const int rem = i & 127;
        const int by = rem >> 3, bx = rem & 7;
        tp64(HW1 + (long long)head * 1024 * 512,
             g_hw1t + (long long)head * 512 * 1024, nullptr,
             1024, 512, 1024, by * 64, bx * 64, t, tid);
    } else {
        const int i = b - 17544;
        const int head = i >> 5;
        const int rem = i & 31;
        const int by = rem >> 2, bx = rem & 3;
        tp64(HW2 + (long long)head * 512 * 256,
             g_hw2t + (long long)head * 256 * 512, nullptr,
             512, 256, 512, by * 64, bx * 64, t, tid);
    }
}

// ============ unified mma.sync GEMM, templated BM/BN/K ======================
// C = act( (A[+Al]) @ (B[+Bl])^T * [alpha] + beta ) ; passes AhBh(+AhBl)(+AlBh)
// BM=128 -> 256 threads / 8 warps / 2 CTAs/SM ; BM=64 -> 128 threads / 4 warps
// / 4 CTAs/SM (finer barriers, more independent CTA streams per SM).
// Warp tile 32 x (BN/2). K-chunk 64, 2-stage smem double buffer.
// KT: compile-time K (== lda of A and row stride of B).
// OUTMODE: 0 = fp32, 1 = fp16 hi, 2 = fp16 hi+lo split.
template <int BM, int BN, int KT, bool SA, bool SB, bool HASALPHA, bool RELU, int OUTMODE>
__global__ __launch_bounds__(BM == 64 ? 128 : 256, BM == 64 ? 4 : 2)
void hmma_gemm_kernel(const __half* __restrict__ Ah, const __half* __restrict__ Al,
                      long long sA,
                      const __half* __restrict__ Bh, const __half* __restrict__ Bl,
                      long long sB,
                      const float* __restrict__ alpha,
                      const float* __restrict__ bias, int sBias,
                      float* __restrict__ Cf, __half* __restrict__ Ch,
                      __half* __restrict__ Cl,
                      long long sC, int ldc) {
    constexpr int NT = BM == 64 ? 128 : 256;  // threads
    constexpr int TA = BM * 128;              // A tile bytes
    constexpr int TB = BN * 128;
    constexpr int OFF_AL = TA;                // iff SA
    constexpr int OFF_B  = (SA ? 2 : 1) * TA;
    constexpr int OFF_BL = OFF_B + TB;        // iff SB
    constexpr int BUF = OFF_B + (SB ? 2 : 1) * TB;
    constexpr int NF = BN / 16;               // n8-frags per warp
    constexpr int NG = BN / 32;               // B ldmatrix groups per warp
    constexpr int NCH = KT >> 6;              // K chunks

    extern __shared__ char smem[];
    const uint32_t sb = smem_to_u32(smem);
    const int tid = threadIdx.x;
    const int lane = tid & 31;
    const int w = tid >> 5;
    const int wm = (w >> 1) * 32;
    const int wn = (w & 1) * (BN / 2);
    const int head = blockIdx.z;
    const int mBase = blockIdx.y * BM;
    const int nBase = blockIdx.x * BN;

    const __half* pA  = Ah + (long long)head * sA + (long long)mBase * KT;
    const __half* pAl = SA ? Al + (long long)head * sA + (long long)mBase * KT : nullptr;
    const __half* pB  = Bh + (long long)head * sB + (long long)nBase * KT;
    const __half* pBl = SB ? Bl + (long long)head * sB + (long long)nBase * KT : nullptr;

    float acc[2][NF][4];
#pragma unroll
    for (int mi = 0; mi < 2; mi++)
#pragma unroll
        for (int n = 0; n < NF; n++)
#pragma unroll
            for (int q = 0; q < 4; q++) acc[mi][n][q] = 0.0f;

    auto load_chunk = [&](uint32_t buf, int kB) {
#pragma unroll
        for (int u = tid; u < BM * 8; u += NT) {      // A rows: BM
            const int r = u >> 3, c = u & 7;
            const uint32_t sw = swz128((uint32_t)(r * 128 + c * 16));
            cp_async16(buf + sw, pA + (long long)r * KT + kB + c * 8);
            if (SA) cp_async16(buf + OFF_AL + sw, pAl + (long long)r * KT + kB + c * 8);
        }
#pragma unroll
        for (int u = tid; u < BN * 8; u += NT) {      // B rows: BN
            const int r = u >> 3, c = u & 7;
            const uint32_t sw = swz128((uint32_t)(r * 128 + c * 16));
            cp_async16(buf + OFF_B + sw, pB + (long long)r * KT + kB + c * 8);
            if (SB) cp_async16(buf + OFF_BL + sw, pBl + (long long)r * KT + kB + c * 8);
        }
    };

    load_chunk(sb, 0);
    CP_COMMIT();

    const int aRowA = wm + (lane & 15);
    const int aRowB = wn + (lane & 15);
    const int cSel  = (lane >> 4);

#pragma unroll 1
    for (int c = 0; c < NCH; ++c) {
        if (c + 1 < NCH) {
            load_chunk(sb + ((c + 1) & 1) * BUF, (c + 1) * 64);
            CP_COMMIT();
            CP_WAIT(1);
        } else {
            CP_WAIT(0);
        }
        __syncthreads();

        const uint32_t bA = sb + (c & 1) * BUF;

#pragma unroll
        for (int ks = 0; ks < 4; ks++) {
            const int kc = ks * 2 + cSel;
            uint32_t ah[2][4], al[2][4];
#pragma unroll
            for (int mi = 0; mi < 2; mi++) {
                const uint32_t ad = swz128((uint32_t)((aRowA + mi * 16) * 128 + kc * 16));
                LDMX4(ah[mi], bA + ad);
                if (SA) LDMX4(al[mi], bA + OFF_AL + ad);
            }
#pragma unroll
            for (int g = 0; g < NG; g++) {
                uint32_t bh[4], bl[4];
                const uint32_t bd = swz128((uint32_t)((aRowB + g * 16) * 128 + kc * 16));
                LDMX4(bh, bA + OFF_B + bd);
                if (SB) LDMX4(bl, bA + OFF_BL + bd);
#pragma unroll
                for (int mi = 0; mi < 2; mi++)
#pragma unroll
                    for (int s = 0; s < 2; s++) {
                        const int n = g * 2 + s;
                        MMA_F16(acc[mi][n], ah[mi], bh[s], bh[s + 2]);
                        if (SB) MMA_F16(acc[mi][n], ah[mi], bl[s], bl[s + 2]);
                        if (SA) MMA_F16(acc[mi][n], al[mi], bh[s], bh[s + 2]);
                    }
            }
        }
        __syncthreads();
    }

    // -------------------------------- epilogue ------------------------------
    const float* bp = bias + (long long)head * sBias + nBase;
    const float* ap = HASALPHA ? alpha + nBase : nullptr;
#pragma unroll
    for (int mi = 0; mi < 2; mi++) {
        const int r0 = mBase + wm + mi * 16 + (lane >> 2);
#pragma unroll
        for (int n = 0; n < NF; n++) {
            const int colL = wn + n * 8 + (lane & 3) * 2;
            const float b0 = __ldg(bp + colL);
            const float b1 = __ldg(bp + colL + 1);
            float a0c = 1.0f, a1c = 1.0f;
            if (HASALPHA) { a0c = __ldg(ap + colL); a1c = __ldg(ap + colL + 1); }
#pragma unroll
            for (int rr = 0; rr < 2; rr++) {
                float v0 = HASALPHA ? fmaf(acc[mi][n][rr * 2 + 0], a0c, b0)
                                    : acc[mi][n][rr * 2 + 0] + b0;
                float v1 = HASALPHA ? fmaf(acc[mi][n][rr * 2 + 1], a1c, b1)
                                    : acc[mi][n][rr * 2 + 1] + b1;
                if (RELU) { v0 = fmaxf(v0, 0.0f); v1 = fmaxf(v1, 0.0f); }
                const long long o = (long long)head * sC +
                                    (long long)(r0 + rr * 8) * ldc + nBase + colL;
                if (OUTMODE == 0) {
                    *(float2*)(Cf + o) = make_float2(v0, v1);
                } else if (OUTMODE == 1) {
                    *(uint32_t*)(Ch + o) = pack_h2(__float2half(v0), __float2half(v1));
                } else {
                    __half h0 = __float2half(v0), h1 = __float2half(v1);
                    *(uint32_t*)(Ch + o) = pack_h2(h0, h1);
                    *(uint32_t*)(Cl + o) =
                        pack_h2(__float2half(v0 - __half2float(h0)),
                                __float2half(v1 - __half2float(h1)));
                }
            }
        }
    }
}

// ================================ launcher ==================================
extern "C" void kernel_launch(void* const* d_in, const int* in_sizes, int n_in,
                              void* d_out, int out_size) {
    const float* x   = (const float*)d_in[0];
    const float* W0  = (const float*)d_in[1];
    const float* b0  = (const float*)d_in[2];
    const float* g0  = (const float*)d_in[3];
    const float* be0 = (const float*)d_in[4];
    const float* m0  = (const float*)d_in[5];
    const float* v0  = (const float*)d_in[6];
    const float* W1  = (const float*)d_in[7];
    const float* b1  = (const float*)d_in[8];
    const float* g1  = (const float*)d_in[9];
    const float* be1 = (const float*)d_in[10];
    const float* m1  = (const float*)d_in[11];
    const float* v1  = (const float*)d_in[12];
    const float* HW1 = (const float*)d_in[13];
    const float* Hb1 = (const float*)d_in[14];
    const float* HW2 = (const float*)d_in[15];
    const float* Hb2 = (const float*)d_in[16];
    float* out = (float*)d_out;

    float *a0, *bb0, *a1, *bb1;
    __half *xh, *xl, *w0th, *w0tl, *hh, *hl, *w1th, *w1tl, *fh, *hw1t, *hw2t, *zh;
    cudaGetSymbolAddress((void**)&xh,   g_xh);
    cudaGetSymbolAddress((void**)&xl,   g_xl);
    cudaGetSymbolAddress((void**)&w0th, g_w0th);
    cudaGetSymbolAddress((void**)&w0tl, g_w0tl);
    cudaGetSymbolAddress((void**)&hh,   g_hh);
    cudaGetSymbolAddress((void**)&hl,   g_hl);
    cudaGetSymbolAddress((void**)&w1th, g_w1th);
    cudaGetSymbolAddress((void**)&w1tl, g_w1tl);
    cudaGetSymbolAddress((void**)&fh,   g_fh);
    cudaGetSymbolAddress((void**)&hw1t, g_hw1t);
    cudaGetSymbolAddress((void**)&hw2t, g_hw2t);
    cudaGetSymbolAddress((void**)&zh,   g_zh);
    cudaGetSymbolAddress((void**)&a0,   g_a0);
    cudaGetSymbolAddress((void**)&bb0,  g_bb0);
    cudaGetSymbolAddress((void**)&a1,   g_a1);
    cudaGetSymbolAddress((void**)&bb1,  g_bb1);

    cudaFuncSetAttribute(hmma_gemm_kernel<128, 64, 256, true, true, true, true, 2>,
                         cudaFuncAttributeMaxDynamicSharedMemorySize, 98304);
    cudaFuncSetAttribute(hmma_gemm_kernel<128, 64, 2048, true, true, true, true, 1>,
                         cudaFuncAttributeMaxDynamicSharedMemorySize, 98304);
    cudaFuncSetAttribute(hmma_gemm_kernel<64, 128, 1024, false, false, false, true, 1>,
                         cudaFuncAttributeMaxDynamicSharedMemorySize, 49152);
    cudaFuncSetAttribute(hmma_gemm_kernel<64, 128, 512, false, false, false, false, 0>,
                         cudaFuncAttributeMaxDynamicSharedMemorySize, 49152);

    // 0) single fused prep launch
    prep_all_kernel<<<21640, 256>>>(x, W0, W1, HW1, HW2,
                                    b0, g0, be0, m0, v0, b1, g1, be1, m1, v1);

    // 1) h = relu(BN(x @ W0 + b0))   3-pass split HMMA -> fp16 hi/lo
    hmma_gemm_kernel<128, 64, 256, true, true, true, true, 2>
        <<<dim3(32, 8, 1), 256, 98304>>>(
        xh, xl, 0LL, w0th, w0tl, 0LL,
        a0, bb0, 0,
        nullptr, hh, hl, 0LL, 2048);

    // 2) feats = relu(BN(h @ W1 + b1))  3-pass split HMMA -> fp16
    hmma_gemm_kernel<128, 64, 2048, true, true, true, true, 1>
        <<<dim3(16, 8, 1), 256, 98304>>>(
        hh, hl, 0LL, w1th, w1tl, 0LL,
        a1, bb1, 0,
        nullptr, fh, nullptr, 0LL, 1024);

    // 3) z[n] = relu(feats @ HW1[n] + Hb1[n])  1-pass fp16, 4-warp CTAs
    hmma_gemm_kernel<64, 128, 1024, false, false, false, true, 1>
        <<<dim3(4, 16, 128), 128, 49152>>>(
        fh, nullptr, 0LL, hw1t, nullptr, 512LL * 1024,
        nullptr, Hb1, 512,
        nullptr, zh, nullptr, 1024LL * 512, 512);

    // 4) out[:,n,:] = z[n] @ HW2[n] + Hb2[n]  1-pass fp16 -> fp32, 4-warp CTAs
    hmma_gemm_kernel<64, 128, 512, false, false, false, false, 0>
        <<<dim3(2, 16, 128), 128, 49152>>>(
        zh, nullptr, 1024LL * 512, hw2t, nullptr, 256LL * 512,
        nullptr, Hb2, 256,
        out, nullptr, nullptr, 256LL, 128 * 256);
}

// round 13
// speedup vs baseline: 1.0548x; 1.0548x over previous
#include <cuda_runtime.h>
#include <cuda_fp16.h>
#include <cstdint>

#define BN_EPS 1e-5f

// ======================= device scratch (no allocs allowed) =================
static __device__ __half g_xh[1024 * 256];                // x hi, K padded to 256
static __device__ __half g_xl[1024 * 256];                // x lo
static __device__ __half g_w0th[2048 * 256];              // W0^T hi [2048][256]
static __device__ __half g_w0tl[2048 * 256];              // W0^T lo
static __device__ __half g_hh[1024 * 2048];               // trunk hidden hi
static __device__ __half g_hl[1024 * 2048];               // trunk hidden lo
static __device__ __half g_w1th[1024 * 2048];             // W1^T hi [1024][2048]
static __device__ __half g_w1tl[1024 * 2048];             // W1^T lo
static __device__ __half g_fh[1024 * 1024];               // feats fp16
static __device__ __half g_hw1t[128u * 512u * 1024u];     // HW1^T [n][512][1024]
static __device__ __half g_hw2t[128u * 256u * 512u];      // HW2^T [n][256][512]
static __device__ __half g_zh[128u * 1024u * 512u];       // z fp16 [n][1024][512]
static __device__ float g_a0[2048], g_bb0[2048];
static __device__ float g_a1[1024], g_bb1[1024];

// ======================= small helpers ======================================
__device__ __forceinline__ uint32_t smem_to_u32(const void* p) {
    uint32_t a;
    asm("{ .reg .u64 t; cvta.to.shared.u64 t, %1; cvt.u32.u64 %0, t; }" : "=r"(a) : "l"(p));
    return a;
}
__device__ __forceinline__ uint32_t swz128(uint32_t off) {
    return off ^ ((off >> 3) & 0x70);
}
__device__ __forceinline__ void cp_async16(uint32_t dst, const void* src) {
    asm volatile("cp.async.cg.shared.global [%0], [%1], 16;" :: "r"(dst), "l"(src));
}
#define CP_COMMIT() asm volatile("cp.async.commit_group;" ::: "memory")
#define CP_WAIT(n)  asm volatile("cp.async.wait_group %0;" :: "n"(n) : "memory")

#define LDMX4(r, addr) \
    asm volatile("ldmatrix.sync.aligned.m8n8.x4.shared.b16 {%0,%1,%2,%3}, [%4];" \
        : "=r"((r)[0]), "=r"((r)[1]), "=r"((r)[2]), "=r"((r)[3]) : "r"(addr))

#define MMA_F16(d, a, b0_, b1_) \
    asm volatile("mma.sync.aligned.m16n8k16.row.col.f32.f16.f16.f32 " \
        "{%0,%1,%2,%3}, {%4,%5,%6,%7}, {%8,%9}, {%0,%1,%2,%3};" \
        : "+f"((d)[0]), "+f"((d)[1]), "+f"((d)[2]), "+f"((d)[3]) \
        : "r"((a)[0]), "r"((a)[1]), "r"((a)[2]), "r"((a)[3]), "r"(b0_), "r"(b1_))

__device__ __forceinline__ uint32_t pack_h2(__half lo16, __half hi16) {
    return ((uint32_t)__half_as_ushort(hi16) << 16) | __half_as_ushort(lo16);
}

// ================= prep: 64x64 transpose-split, uint4 stores ================
__device__ __forceinline__ void tp64(const float* __restrict__ in,
                                     __half* __restrict__ oh, __half* __restrict__ ol,
                                     int R, int C, int Rpad, int r0, int c0,
                                     float* t, int tid) {
#pragma unroll
    for (int k = 0; k < 4; k++) {
        const int u = tid + k * 256;
        const int r = u >> 4;
        const int cq = (u & 15) * 4;
        const int gr = r0 + r;
        float4 v = make_float4(0.f, 0.f, 0.f, 0.f);
        if (gr < R) v = *(const float4*)(in + (long long)gr * C + c0 + cq);
        t[r * 65 + cq]     = v.x;
        t[r * 65 + cq + 1] = v.y;
        t[r * 65 + cq + 2] = v.z;
        t[r * 65 + cq + 3] = v.w;
    }
    __syncthreads();
#pragma unroll
    for (int k = 0; k < 2; k++) {
        const int u = tid + k * 256;
        const int cc = u >> 3;            // output row (source column) 0..63
        const int r8 = (u & 7) * 8;       // 8 consecutive output cols
        uint32_t hp[4], lp[4];
#pragma unroll
        for (int j = 0; j < 4; j++) {
            const float v0 = t[(r8 + 2 * j) * 65 + cc];
            const float v1 = t[(r8 + 2 * j + 1) * 65 + cc];
            const __half h0 = __float2half(v0), h1 = __float2half(v1);
            hp[j] = pack_h2(h0, h1);
            if (ol) lp[j] = pack_h2(__float2half(v0 - __half2float(h0)),
                                    __float2half(v1 - __half2float(h1)));
        }
        const long long o = (long long)(c0 + cc) * Rpad + r0 + r8;
        *(uint4*)(oh + o) = make_uint4(hp[0], hp[1], hp[2], hp[3]);
        if (ol) *(uint4*)(ol + o) = make_uint4(lp[0], lp[1], lp[2], lp[3]);
    }
}

// ---- trunk prep: bnfold 8 | xconv 512 | W0T 128 | W1T 512  => 1160 blocks --
__global__ __launch_bounds__(256)
void prep_trunk_kernel(const float* __restrict__ x,
                       const float* __restrict__ W0, const float* __restrict__ W1,
                       const float* __restrict__ b0, const float* __restrict__ g0,
                       const float* __restrict__ be0, const float* __restrict__ m0,
                       const float* __restrict__ v0,
                       const float* __restrict__ b1, const float* __restrict__ g1,
                       const float* __restrict__ be1, const float* __restrict__ m1,
                       const float* __restrict__ v1) {
    __shared__ float t[64 * 65];
    const int tid = threadIdx.x;
    const int b = blockIdx.x;

    if (b < 8) {
        const int i = b * 256 + tid;
        if (i < 2048) {
            float a = g0[i] / sqrtf(v0[i] + BN_EPS);
            g_a0[i]  = a;
            g_bb0[i] = be0[i] + (b0[i] - m0[i]) * a;
        }
        if (i < 1024) {
            float a = g1[i] / sqrtf(v1[i] + BN_EPS);
            g_a1[i]  = a;
            g_bb1[i] = be1[i] + (b1[i] - m1[i]) * a;
        }
    } else if (b < 520) {
        const int u = (b - 8) * 256 + tid;
        const int row = u >> 7;
        const int c2 = (u & 127) * 2;
        float v0 = (c2     < 200) ? x[row * 200 + c2]     : 0.f;
        float v1 = (c2 + 1 < 200) ? x[row * 200 + c2 + 1] : 0.f;
        __half h0 = __float2half(v0), h1 = __float2half(v1);
        *(uint32_t*)(g_xh + row * 256 + c2) = pack_h2(h0, h1);
        *(uint32_t*)(g_xl + row * 256 + c2) =
            pack_h2(__float2half(v0 - __half2float(h0)),
                    __float2half(v1 - __half2float(h1)));
    } else if (b < 648) {
        const int i = b - 520;
        const int by = i >> 5, bx = i & 31;
        tp64(W0, g_w0th, g_w0tl, 200, 2048, 256, by * 64, bx * 64, t, tid);
    } else {
        const int i = b - 648;
        const int by = i >> 4, bx = i & 15;
        tp64(W1, g_w1th, g_w1tl, 2048, 1024, 2048, by * 64, bx * 64, t, tid);
    }
}

// ---- head prep: HW1T 16384 | HW2T 4096  => 20480 blocks --------------------
__global__ __launch_bounds__(256)
void prep_heads_kernel(const float* __restrict__ HW1, const float* __restrict__ HW2) {
    __shared__ float t[64 * 65];
    const int tid = threadIdx.x;
    const int b = blockIdx.x;
    if (b < 16384) {
        const int head = b >> 7;
        const int rem = b & 127;
        const int by = rem >> 3, bx = rem & 7;
        tp64(HW1 + (long long)head * 1024 * 512,
             g_hw1t + (long long)head * 512 * 1024, nullptr,
             1024, 512, 1024, by * 64, bx * 64, t, tid);
    } else {
        const int i = b - 16384;
        const int head = i >> 5;
        const int rem = i & 31;
        const int by = rem >> 2, bx = rem & 3;
        tp64(HW2 + (long long)head * 512 * 256,
             g_hw2t + (long long)head * 256 * 512, nullptr,
             512, 256, 512, by * 64, bx * 64, t, tid);
    }
}

// ============ unified mma.sync GEMM (R7 shape), templated BN / KT ===========
// C = act( (A[+Al]) @ (B[+Bl])^T * [alpha] + beta ) ; passes AhBh(+AhBl)(+AlBh)
// BM=128, 8 warps, warp tile 32 x (BN/2), K-chunk 64, 2-stage double buffer,
// 2 CTAs/SM. OUTMODE: 0 = fp32, 1 = fp16 hi, 2 = fp16 hi+lo split.
template <int BN, int KT, bool SA, bool SB, bool HASALPHA, bool RELU, int OUTMODE>
__global__ __launch_bounds__(256, 2)
void hmma_gemm_kernel(const __half* __restrict__ Ah, const __half* __restrict__ Al,
                      long long sA,
                      const __half* __restrict__ Bh, const __half* __restrict__ Bl,
                      long long sB,
                      const float* __restrict__ alpha,
                      const float* __restrict__ bias, int sBias,
                      float* __restrict__ Cf, __half* __restrict__ Ch,
                      __half* __restrict__ Cl,
                      long long sC, int ldc) {
    constexpr int TA = 16384;                 // 128 rows x 128 B
    constexpr int TB = BN * 128;
    constexpr int OFF_AL = TA;                // iff SA
    constexpr int OFF_B  = (SA ? 2 : 1) * TA;
    constexpr int OFF_BL = OFF_B + TB;        // iff SB
    constexpr int BUF = OFF_B + (SB ? 2 : 1) * TB;
    constexpr int NF = BN / 16;               // n8-frags per warp
    constexpr int NG = BN / 32;               // B ldmatrix groups per warp
    constexpr int NCH = KT >> 6;              // K chunks

    extern __shared__ char smem[];
    const uint32_t sb = smem_to_u32(smem);
    const int tid = threadIdx.x;
    const int lane = tid & 31;
    const int w = tid >> 5;
    const int wm = (w >> 1) * 32;
    const int wn = (w & 1) * (BN / 2);
    const int head = blockIdx.z;
    const int mBase = blockIdx.y * 128;
    const int nBase = blockIdx.x * BN;

    const __half* pA  = Ah + (long long)head * sA + (long long)mBase * KT;
    const __half* pAl = SA ? Al + (long long)head * sA + (long long)mBase * KT : nullptr;
    const __half* pB  = Bh + (long long)head * sB + (long long)nBase * KT;
    const __half* pBl = SB ? Bl + (long long)head * sB + (long long)nBase * KT : nullptr;

    float acc[2][NF][4];
#pragma unroll
    for (int mi = 0; mi < 2; mi++)
#pragma unroll
        for (int n = 0; n < NF; n++)
#pragma unroll
            for (int q = 0; q < 4; q++) acc[mi][n][q] = 0.0f;

    auto load_chunk = [&](uint32_t buf, int kB) {
#pragma unroll
        for (int u = tid; u < 1024; u += 256) {       // A rows: 128
            const int r = u >> 3, c = u & 7;
            const uint32_t sw = swz128((uint32_t)(r * 128 + c * 16));
            cp_async16(buf + sw, pA + (long long)r * KT + kB + c * 8);
            if (SA) cp_async16(buf + OFF_AL + sw, pAl + (long long)r * KT + kB + c * 8);
        }
#pragma unroll
        for (int u = tid; u < BN * 8; u += 256) {     // B rows: BN
            const int r = u >> 3, c = u & 7;
            const uint32_t sw = swz128((uint32_t)(r * 128 + c * 16));
            cp_async16(buf + OFF_B + sw, pB + (long long)r * KT + kB + c * 8);
            if (SB) cp_async16(buf + OFF_BL + sw, pBl + (long long)r * KT + kB + c * 8);
        }
    };

    load_chunk(sb, 0);
    CP_COMMIT();

    const int aRowA = wm + (lane & 15);
    const int aRowB = wn + (lane & 15);
    const int cSel  = (lane >> 4);

#pragma unroll 1
    for (int c = 0; c < NCH; ++c) {
        if (c + 1 < NCH) {
            load_chunk(sb + ((c + 1) & 1) * BUF, (c + 1) * 64);
            CP_COMMIT();
            CP_WAIT(1);
        } else {
            CP_WAIT(0);
        }
        __syncthreads();

        const uint32_t bA = sb + (c & 1) * BUF;

#pragma unroll
        for (int ks = 0; ks < 4; ks++) {
            const int kc = ks * 2 + cSel;
            uint32_t ah[2][4], al[2][4];
#pragma unroll
            for (int mi = 0; mi < 2; mi++) {
                const uint32_t ad = swz128((uint32_t)((aRowA + mi * 16) * 128 + kc * 16));
                LDMX4(ah[mi], bA + ad);
                if (SA) LDMX4(al[mi], bA + OFF_AL + ad);
            }
#pragma unroll
            for (int g = 0; g < NG; g++) {
                uint32_t bh[4], bl[4];
                const uint32_t bd = swz128((uint32_t)((aRowB + g * 16) * 128 + kc * 16));
                LDMX4(bh, bA + OFF_B + bd);
                if (SB) LDMX4(bl, bA + OFF_BL + bd);
#pragma unroll
                for (int mi = 0; mi < 2; mi++)
#pragma unroll
                    for (int s = 0; s < 2; s++) {
                        const int n = g * 2 + s;
                        MMA_F16(acc[mi][n], ah[mi], bh[s], bh[s + 2]);
                        if (SB) MMA_F16(acc[mi][n], ah[mi], bl[s], bl[s + 2]);
                        if (SA) MMA_F16(acc[mi][n], al[mi], bh[s], bh[s + 2]);
                    }
            }
        }
        __syncthreads();
    }

    // -------------------------------- epilogue ------------------------------
    const float* bp = bias + (long long)head * sBias + nBase;
    const float* ap = HASALPHA ? alpha + nBase : nullptr;
#pragma unroll
    for (int mi = 0; mi < 2; mi++) {
        const int r0 = mBase + wm + mi * 16 + (lane >> 2);
#pragma unroll
        for (int n = 0; n < NF; n++) {
            const int colL = wn + n * 8 + (lane & 3) * 2;
            const float b0 = __ldg(bp + colL);
            const float b1 = __ldg(bp + colL + 1);
            float a0c = 1.0f, a1c = 1.0f;
            if (HASALPHA) { a0c = __ldg(ap + colL); a1c = __ldg(ap + colL + 1); }
#pragma unroll
            for (int rr = 0; rr < 2; rr++) {
                float v0 = HASALPHA ? fmaf(acc[mi][n][rr * 2 + 0], a0c, b0)
                                    : acc[mi][n][rr * 2 + 0] + b0;
                float v1 = HASALPHA ? fmaf(acc[mi][n][rr * 2 + 1], a1c, b1)
                                    : acc[mi][n][rr * 2 + 1] + b1;
                if (RELU) { v0 = fmaxf(v0, 0.0f); v1 = fmaxf(v1, 0.0f); }
                const long long o = (long long)head * sC +
                                    (long long)(r0 + rr * 8) * ldc + nBase + colL;
                if (OUTMODE == 0) {
                    *(float2*)(Cf + o) = make_float2(v0, v1);
                } else if (OUTMODE == 1) {
                    *(uint32_t*)(Ch + o) = pack_h2(__float2half(v0), __float2half(v1));
                } else {
                    __half h0 = __float2half(v0), h1 = __float2half(v1);
                    *(uint32_t*)(Ch + o) = pack_h2(h0, h1);
                    *(uint32_t*)(Cl + o) =
                        pack_h2(__float2half(v0 - __half2float(h0)),
                                __float2half(v1 - __half2float(h1)));
                }
            }
        }
    }
}

// ================================ launcher ==================================
extern "C" void kernel_launch(void* const* d_in, const int* in_sizes, int n_in,
                              void* d_out, int out_size) {
    const float* x   = (const float*)d_in[0];
    const float* W0  = (const float*)d_in[1];
    const float* b0  = (const float*)d_in[2];
    const float* g0  = (const float*)d_in[3];
    const float* be0 = (const float*)d_in[4];
    const float* m0  = (const float*)d_in[5];
    const float* v0  = (const float*)d_in[6];
    const float* W1  = (const float*)d_in[7];
    const float* b1  = (const float*)d_in[8];
    const float* g1  = (const float*)d_in[9];
    const float* be1 = (const float*)d_in[10];
    const float* m1  = (const float*)d_in[11];
    const float* v1  = (const float*)d_in[12];
    const float* HW1 = (const float*)d_in[13];
    const float* Hb1 = (const float*)d_in[14];
    const float* HW2 = (const float*)d_in[15];
    const float* Hb2 = (const float*)d_in[16];
    float* out = (float*)d_out;

    float *a0, *bb0, *a1, *bb1;
    __half *xh, *xl, *w0th, *w0tl, *hh, *hl, *w1th, *w1tl, *fh, *hw1t, *hw2t, *zh;
    cudaGetSymbolAddress((void**)&xh,   g_xh);
    cudaGetSymbolAddress((void**)&xl,   g_xl);
    cudaGetSymbolAddress((void**)&w0th, g_w0th);
    cudaGetSymbolAddress((void**)&w0tl, g_w0tl);
    cudaGetSymbolAddress((void**)&hh,   g_hh);
    cudaGetSymbolAddress((void**)&hl,   g_hl);
    cudaGetSymbolAddress((void**)&w1th, g_w1th);
    cudaGetSymbolAddress((void**)&w1tl, g_w1tl);
    cudaGetSymbolAddress((void**)&fh,   g_fh);
    cudaGetSymbolAddress((void**)&hw1t, g_hw1t);
    cudaGetSymbolAddress((void**)&hw2t, g_hw2t);
    cudaGetSymbolAddress((void**)&zh,   g_zh);
    cudaGetSymbolAddress((void**)&a0,   g_a0);
    cudaGetSymbolAddress((void**)&bb0,  g_bb0);
    cudaGetSymbolAddress((void**)&a1,   g_a1);
    cudaGetSymbolAddress((void**)&bb1,  g_bb1);

    cudaFuncSetAttribute(hmma_gemm_kernel<64, 256, true, true, true, true, 2>,
                         cudaFuncAttributeMaxDynamicSharedMemorySize, 98304);
    cudaFuncSetAttribute(hmma_gemm_kernel<64, 2048, true, true, true, true, 1>,
                         cudaFuncAttributeMaxDynamicSharedMemorySize, 98304);
    cudaFuncSetAttribute(hmma_gemm_kernel<128, 1024, false, false, false, true, 1>,
                         cudaFuncAttributeMaxDynamicSharedMemorySize, 65536);
    cudaFuncSetAttribute(hmma_gemm_kernel<128, 512, false, false, false, false, 0>,
                         cudaFuncAttributeMaxDynamicSharedMemorySize, 65536);

    // lazy aux stream + events (created on the uncaptured correctness call;
    // reused as capture-legal fork/join nodes afterwards)
    static cudaStream_t auxStream = nullptr;
    static cudaEvent_t evFork = nullptr, evHeads = nullptr;
    static int triedInit = 0;
    if (!triedInit) {
        triedInit = 1;
        if (cudaStreamCreateWithFlags(&auxStream, cudaStreamNonBlocking) != cudaSuccess)
            auxStream = nullptr;
        if (auxStream) {
            if (cudaEventCreateWithFlags(&evFork, cudaEventDisableTiming) != cudaSuccess ||
                cudaEventCreateWithFlags(&evHeads, cudaEventDisableTiming) != cudaSuccess)
                auxStream = nullptr;
        }
    }

    if (auxStream) {
        // fork: head-weight prep runs concurrently with trunk chain
        cudaEventRecord(evFork, 0);
        cudaStreamWaitEvent(auxStream, evFork, 0);
        prep_heads_kernel<<<20480, 256, 0, auxStream>>>(HW1, HW2);
        cudaEventRecord(evHeads, auxStream);
    }

    // trunk chain on default stream
    prep_trunk_kernel<<<1160, 256>>>(x, W0, W1,
                                     b0, g0, be0, m0, v0, b1, g1, be1, m1, v1);

    // 1) h = relu(BN(x @ W0 + b0))   3-pass split HMMA -> fp16 hi/lo
    hmma_gemm_kernel<64, 256, true, true, true, true, 2>
        <<<dim3(32, 8, 1), 256, 98304>>>(
        xh, xl, 0LL, w0th, w0tl, 0LL,
        a0, bb0, 0,
        nullptr, hh, hl, 0LL, 2048);

    // 2) feats = relu(BN(h @ W1 + b1))  3-pass split HMMA -> fp16
    hmma_gemm_kernel<64, 2048, true, true, true, true, 1>
        <<<dim3(16, 8, 1), 256, 98304>>>(
        hh, hl, 0LL, w1th, w1tl, 0LL,
        a1, bb1, 0,
        nullptr, fh, nullptr, 0LL, 1024);

    if (auxStream) {
        // join: stage 3 needs the converted head weights
        cudaStreamWaitEvent(0, evHeads, 0);
    } else {
        prep_heads_kernel<<<20480, 256>>>(HW1, HW2);
    }

    // 3) z[n] = relu(feats @ HW1[n] + Hb1[n])  1-pass fp16 -> fp16
    hmma_gemm_kernel<128, 1024, false, false, false, true, 1>
        <<<dim3(4, 8, 128), 256, 65536>>>(
        fh, nullptr, 0LL, hw1t, nullptr, 512LL * 1024,
        nullptr, Hb1, 512,
        nullptr, zh, nullptr, 1024LL * 512, 512);

    // 4) out[:,n,:] = z[n] @ HW2[n] + Hb2[n]  1-pass fp16 -> fp32
    hmma_gemm_kernel<128, 512, false, false, false, false, 0>
        <<<dim3(2, 8, 128), 256, 65536>>>(
        zh, nullptr, 1024LL * 512, hw2t, nullptr, 256LL * 512,
        nullptr, Hb2, 256,
        out, nullptr, nullptr, 256LL, 128 * 256);
}

// round 14
// speedup vs baseline: 1.1012x; 1.0440x over previous
#include <cuda_runtime.h>
#include <cuda_fp16.h>
#include <cstdint>

#define BN_EPS 1e-5f

// ======================= device scratch (no allocs allowed) =================
static __device__ __half g_xh[1024 * 256];                // x hi, K padded to 256
static __device__ __half g_xl[1024 * 256];                // x lo
static __device__ __half g_w0th[2048 * 256];              // W0^T hi [2048][256]
static __device__ __half g_w0tl[2048 * 256];              // W0^T lo
static __device__ __half g_hh[1024 * 2048];               // trunk hidden (fp16)
static __device__ __half g_w1th[1024 * 2048];             // W1^T hi [1024][2048]
static __device__ __half g_fh[1024 * 1024];               // feats fp16
static __device__ __half g_hw1t[128u * 512u * 1024u];     // HW1^T [n][512][1024]
static __device__ __half g_hw2t[128u * 256u * 512u];      // HW2^T [n][256][512]
static __device__ __half g_zh[128u * 1024u * 512u];       // z fp16 [n][1024][512]
static __device__ float g_a0[2048], g_bb0[2048];
static __device__ float g_a1[1024], g_bb1[1024];

// ======================= small helpers ======================================
__device__ __forceinline__ uint32_t smem_to_u32(const void* p) {
    uint32_t a;
    asm("{ .reg .u64 t; cvta.to.shared.u64 t, %1; cvt.u32.u64 %0, t; }" : "=r"(a) : "l"(p));
    return a;
}
__device__ __forceinline__ uint32_t swz128(uint32_t off) {
    return off ^ ((off >> 3) & 0x70);
}
__device__ __forceinline__ void cp_async16(uint32_t dst, const void* src) {
    asm volatile("cp.async.cg.shared.global [%0], [%1], 16;" :: "r"(dst), "l"(src));
}
#define CP_COMMIT() asm volatile("cp.async.commit_group;" ::: "memory")
#define CP_WAIT(n)  asm volatile("cp.async.wait_group %0;" :: "n"(n) : "memory")

#define LDMX4(r, addr) \
    asm volatile("ldmatrix.sync.aligned.m8n8.x4.shared.b16 {%0,%1,%2,%3}, [%4];" \
        : "=r"((r)[0]), "=r"((r)[1]), "=r"((r)[2]), "=r"((r)[3]) : "r"(addr))

#define MMA_F16(d, a, b0_, b1_) \
    asm volatile("mma.sync.aligned.m16n8k16.row.col.f32.f16.f16.f32 " \
        "{%0,%1,%2,%3}, {%4,%5,%6,%7}, {%8,%9}, {%0,%1,%2,%3};" \
        : "+f"((d)[0]), "+f"((d)[1]), "+f"((d)[2]), "+f"((d)[3]) \
        : "r"((a)[0]), "r"((a)[1]), "r"((a)[2]), "r"((a)[3]), "r"(b0_), "r"(b1_))

__device__ __forceinline__ uint32_t pack_h2(__half lo16, __half hi16) {
    return ((uint32_t)__half_as_ushort(hi16) << 16) | __half_as_ushort(lo16);
}

// ================= prep: 64x64 transpose-split, uint4 stores ================
__device__ __forceinline__ void tp64(const float* __restrict__ in,
                                     __half* __restrict__ oh, __half* __restrict__ ol,
                                     int R, int C, int Rpad, int r0, int c0,
                                     float* t, int tid) {
#pragma unroll
    for (int k = 0; k < 4; k++) {
        const int u = tid + k * 256;
        const int r = u >> 4;
        const int cq = (u & 15) * 4;
        const int gr = r0 + r;
        float4 v = make_float4(0.f, 0.f, 0.f, 0.f);
        if (gr < R) v = *(const float4*)(in + (long long)gr * C + c0 + cq);
        t[r * 65 + cq]     = v.x;
        t[r * 65 + cq + 1] = v.y;
        t[r * 65 + cq + 2] = v.z;
        t[r * 65 + cq + 3] = v.w;
    }
    __syncthreads();
#pragma unroll
    for (int k = 0; k < 2; k++) {
        const int u = tid + k * 256;
        const int cc = u >> 3;            // output row (source column) 0..63
        const int r8 = (u & 7) * 8;       // 8 consecutive output cols
        uint32_t hp[4], lp[4];
#pragma unroll
        for (int j = 0; j < 4; j++) {
            const float v0 = t[(r8 + 2 * j) * 65 + cc];
            const float v1 = t[(r8 + 2 * j + 1) * 65 + cc];
            const __half h0 = __float2half(v0), h1 = __float2half(v1);
            hp[j] = pack_h2(h0, h1);
            if (ol) lp[j] = pack_h2(__float2half(v0 - __half2float(h0)),
                                    __float2half(v1 - __half2float(h1)));
        }
        const long long o = (long long)(c0 + cc) * Rpad + r0 + r8;
        *(uint4*)(oh + o) = make_uint4(hp[0], hp[1], hp[2], hp[3]);
        if (ol) *(uint4*)(ol + o) = make_uint4(lp[0], lp[1], lp[2], lp[3]);
    }
}

// ---- trunk prep: bnfold 8 | xconv 512 | W0T 128 | W1T 512  => 1160 blocks --
__global__ __launch_bounds__(256)
void prep_trunk_kernel(const float* __restrict__ x,
                       const float* __restrict__ W0, const float* __restrict__ W1,
                       const float* __restrict__ b0, const float* __restrict__ g0,
                       const float* __restrict__ be0, const float* __restrict__ m0,
                       const float* __restrict__ v0,
                       const float* __restrict__ b1, const float* __restrict__ g1,
                       const float* __restrict__ be1, const float* __restrict__ m1,
                       const float* __restrict__ v1) {
    __shared__ float t[64 * 65];
    const int tid = threadIdx.x;
    const int b = blockIdx.x;

    if (b < 8) {
        const int i = b * 256 + tid;
        if (i < 2048) {
            float a = g0[i] / sqrtf(v0[i] + BN_EPS);
            g_a0[i]  = a;
            g_bb0[i] = be0[i] + (b0[i] - m0[i]) * a;
        }
        if (i < 1024) {
            float a = g1[i] / sqrtf(v1[i] + BN_EPS);
            g_a1[i]  = a;
            g_bb1[i] = be1[i] + (b1[i] - m1[i]) * a;
        }
    } else if (b < 520) {
        const int u = (b - 8) * 256 + tid;
        const int row = u >> 7;
        const int c2 = (u & 127) * 2;
        float v0 = (c2     < 200) ? x[row * 200 + c2]     : 0.f;
        float v1 = (c2 + 1 < 200) ? x[row * 200 + c2 + 1] : 0.f;
        __half h0 = __float2half(v0), h1 = __float2half(v1);
        *(uint32_t*)(g_xh + row * 256 + c2) = pack_h2(h0, h1);
        *(uint32_t*)(g_xl + row * 256 + c2) =
            pack_h2(__float2half(v0 - __half2float(h0)),
                    __float2half(v1 - __half2float(h1)));
    } else if (b < 648) {
        const int i = b - 520;
        const int by = i >> 5, bx = i & 31;
        tp64(W0, g_w0th, g_w0tl, 200, 2048, 256, by * 64, bx * 64, t, tid);
    } else {
        const int i = b - 648;
        const int by = i >> 4, bx = i & 15;
        tp64(W1, g_w1th, nullptr, 2048, 1024, 2048, by * 64, bx * 64, t, tid);
    }
}

// ---- head prep: HW1T 16384 | HW2T 4096  => 20480 blocks --------------------
__global__ __launch_bounds__(256)
void prep_heads_kernel(const float* __restrict__ HW1, const float* __restrict__ HW2) {
    __shared__ float t[64 * 65];
    const int tid = threadIdx.x;
    const int b = blockIdx.x;
    if (b < 16384) {
        const int head = b >> 7;
        const int rem = b & 127;
        const int by = rem >> 3, bx = rem & 7;
        tp64(HW1 + (long long)head * 1024 * 512,
             g_hw1t + (long long)head * 512 * 1024, nullptr,
             1024, 512, 1024, by * 64, bx * 64, t, tid);
    } else {
        const int i = b - 16384;
        const int head = i >> 5;
        const int rem = i & 31;
        const int by = rem >> 2, bx = rem & 3;
        tp64(HW2 + (long long)head * 512 * 256,
             g_hw2t + (long long)head * 256 * 512, nullptr,
             512, 256, 512, by * 64, bx * 64, t, tid);
    }
}

// ============ unified mma.sync GEMM (R7 shape), templated BN / KT ===========
// C = act( (A[+Al]) @ (B[+Bl])^T * [alpha] + beta ) ; passes AhBh(+AhBl)(+AlBh)
// BM=128, 8 warps, warp tile 32 x (BN/2), K-chunk 64, 2-stage double buffer,
// 2 CTAs/SM. OUTMODE: 0 = fp32, 1 = fp16 hi, 2 = fp16 hi+lo split.
template <int BN, int KT, bool SA, bool SB, bool HASALPHA, bool RELU, int OUTMODE>
__global__ __launch_bounds__(256, 2)
void hmma_gemm_kernel(const __half* __restrict__ Ah, const __half* __restrict__ Al,
                      long long sA,
                      const __half* __restrict__ Bh, const __half* __restrict__ Bl,
                      long long sB,
                      const float* __restrict__ alpha,
                      const float* __restrict__ bias, int sBias,
                      float* __restrict__ Cf, __half* __restrict__ Ch,
                      __half* __restrict__ Cl,
                      long long sC, int ldc) {
    constexpr int TA = 16384;                 // 128 rows x 128 B
    constexpr int TB = BN * 128;
    constexpr int OFF_AL = TA;                // iff SA
    constexpr int OFF_B  = (SA ? 2 : 1) * TA;
    constexpr int OFF_BL = OFF_B + TB;        // iff SB
    constexpr int BUF = OFF_B + (SB ? 2 : 1) * TB;
    constexpr int NF = BN / 16;               // n8-frags per warp
    constexpr int NG = BN / 32;               // B ldmatrix groups per warp
    constexpr int NCH = KT >> 6;              // K chunks

    extern __shared__ char smem[];
    const uint32_t sb = smem_to_u32(smem);
    const int tid = threadIdx.x;
    const int lane = tid & 31;
    const int w = tid >> 5;
    const int wm = (w >> 1) * 32;
    const int wn = (w & 1) * (BN / 2);
    const int head = blockIdx.z;
    const int mBase = blockIdx.y * 128;
    const int nBase = blockIdx.x * BN;

    const __half* pA  = Ah + (long long)head * sA + (long long)mBase * KT;
    const __half* pAl = SA ? Al + (long long)head * sA + (long long)mBase * KT : nullptr;
    const __half* pB  = Bh + (long long)head * sB + (long long)nBase * KT;
    const __half* pBl = SB ? Bl + (long long)head * sB + (long long)nBase * KT : nullptr;

    float acc[2][NF][4];
#pragma unroll
    for (int mi = 0; mi < 2; mi++)
#pragma unroll
        for (int n = 0; n < NF; n++)
#pragma unroll
            for (int q = 0; q < 4; q++) acc[mi][n][q] = 0.0f;

    auto load_chunk = [&](uint32_t buf, int kB) {
#pragma unroll
        for (int u = tid; u < 1024; u += 256) {       // A rows: 128
            const int r = u >> 3, c = u & 7;
            const uint32_t sw = swz128((uint32_t)(r * 128 + c * 16));
            cp_async16(buf + sw, pA + (long long)r * KT + kB + c * 8);
            if (SA) cp_async16(buf + OFF_AL + sw, pAl + (long long)r * KT + kB + c * 8);
        }
#pragma unroll
        for (int u = tid; u < BN * 8; u += 256) {     // B rows: BN
            const int r = u >> 3, c = u & 7;
            const uint32_t sw = swz128((uint32_t)(r * 128 + c * 16));
            cp_async16(buf + OFF_B + sw, pB + (long long)r * KT + kB + c * 8);
            if (SB) cp_async16(buf + OFF_BL + sw, pBl + (long long)r * KT + kB + c * 8);
        }
    };

    load_chunk(sb, 0);
    CP_COMMIT();

    const int aRowA = wm + (lane & 15);
    const int aRowB = wn + (lane & 15);
    const int cSel  = (lane >> 4);

#pragma unroll 1
    for (int c = 0; c < NCH; ++c) {
        if (c + 1 < NCH) {
            load_chunk(sb + ((c + 1) & 1) * BUF, (c + 1) * 64);
            CP_COMMIT();
            CP_WAIT(1);
        } else {
            CP_WAIT(0);
        }
        __syncthreads();

        const uint32_t bA = sb + (c & 1) * BUF;

#pragma unroll
        for (int ks = 0; ks < 4; ks++) {
            const int kc = ks * 2 + cSel;
            uint32_t ah[2][4], al[2][4];
#pragma unroll
            for (int mi = 0; mi < 2; mi++) {
                const uint32_t ad = swz128((uint32_t)((aRowA + mi * 16) * 128 + kc * 16));
                LDMX4(ah[mi], bA + ad);
                if (SA) LDMX4(al[mi], bA + OFF_AL + ad);
            }
#pragma unroll
            for (int g = 0; g < NG; g++) {
                uint32_t bh[4], bl[4];
                const uint32_t bd = swz128((uint32_t)((aRowB + g * 16) * 128 + kc * 16));
                LDMX4(bh, bA + OFF_B + bd);
                if (SB) LDMX4(bl, bA + OFF_BL + bd);
#pragma unroll
                for (int mi = 0; mi < 2; mi++)
#pragma unroll
                    for (int s = 0; s < 2; s++) {
                        const int n = g * 2 + s;
                        MMA_F16(acc[mi][n], ah[mi], bh[s], bh[s + 2]);
                        if (SB) MMA_F16(acc[mi][n], ah[mi], bl[s], bl[s + 2]);
                        if (SA) MMA_F16(acc[mi][n], al[mi], bh[s], bh[s + 2]);
                    }
            }
        }
        __syncthreads();
    }

    // -------------------------------- epilogue ------------------------------
    const float* bp = bias + (long long)head * sBias + nBase;
    const float* ap = HASALPHA ? alpha + nBase : nullptr;
#pragma unroll
    for (int mi = 0; mi < 2; mi++) {
        const int r0 = mBase + wm + mi * 16 + (lane >> 2);
#pragma unroll
        for (int n = 0; n < NF; n++) {
            const int colL = wn + n * 8 + (lane & 3) * 2;
            const float b0 = __ldg(bp + colL);
            const float b1 = __ldg(bp + colL + 1);
            float a0c = 1.0f, a1c = 1.0f;
            if (HASALPHA) { a0c = __ldg(ap + colL); a1c = __ldg(ap + colL + 1); }
#pragma unroll
            for (int rr = 0; rr < 2; rr++) {
                float v0 = HASALPHA ? fmaf(acc[mi][n][rr * 2 + 0], a0c, b0)
                                    : acc[mi][n][rr * 2 + 0] + b0;
                float v1 = HASALPHA ? fmaf(acc[mi][n][rr * 2 + 1], a1c, b1)
                                    : acc[mi][n][rr * 2 + 1] + b1;
                if (RELU) { v0 = fmaxf(v0, 0.0f); v1 = fmaxf(v1, 0.0f); }
                const long long o = (long long)head * sC +
                                    (long long)(r0 + rr * 8) * ldc + nBase + colL;
                if (OUTMODE == 0) {
                    *(float2*)(Cf + o) = make_float2(v0, v1);
                } else if (OUTMODE == 1) {
                    *(uint32_t*)(Ch + o) = pack_h2(__float2half(v0), __float2half(v1));
                } else {
                    __half h0 = __float2half(v0), h1 = __float2half(v1);
                    *(uint32_t*)(Ch + o) = pack_h2(h0, h1);
                    *(uint32_t*)(Cl + o) =
                        pack_h2(__float2half(v0 - __half2float(h0)),
                                __float2half(v1 - __half2float(h1)));
                }
            }
        }
    }
}

// ================================ launcher ==================================
extern "C" void kernel_launch(void* const* d_in, const int* in_sizes, int n_in,
                              void* d_out, int out_size) {
    const float* x   = (const float*)d_in[0];
    const float* W0  = (const float*)d_in[1];
    const float* b0  = (const float*)d_in[2];
    const float* g0  = (const float*)d_in[3];
    const float* be0 = (const float*)d_in[4];
    const float* m0  = (const float*)d_in[5];
    const float* v0  = (const float*)d_in[6];
    const float* W1  = (const float*)d_in[7];
    const float* b1  = (const float*)d_in[8];
    const float* g1  = (const float*)d_in[9];
    const float* be1 = (const float*)d_in[10];
    const float* m1  = (const float*)d_in[11];
    const float* v1  = (const float*)d_in[12];
    const float* HW1 = (const float*)d_in[13];
    const float* Hb1 = (const float*)d_in[14];
    const float* HW2 = (const float*)d_in[15];
    const float* Hb2 = (const float*)d_in[16];
    float* out = (float*)d_out;

    float *a0, *bb0, *a1, *bb1;
    __half *xh, *xl, *w0th, *w0tl, *hh, *w1th, *fh, *hw1t, *hw2t, *zh;
    cudaGetSymbolAddress((void**)&xh,   g_xh);
    cudaGetSymbolAddress((void**)&xl,   g_xl);
    cudaGetSymbolAddress((void**)&w0th, g_w0th);
    cudaGetSymbolAddress((void**)&w0tl, g_w0tl);
    cudaGetSymbolAddress((void**)&hh,   g_hh);
    cudaGetSymbolAddress((void**)&w1th, g_w1th);
    cudaGetSymbolAddress((void**)&fh,   g_fh);
    cudaGetSymbolAddress((void**)&hw1t, g_hw1t);
    cudaGetSymbolAddress((void**)&hw2t, g_hw2t);
    cudaGetSymbolAddress((void**)&zh,   g_zh);
    cudaGetSymbolAddress((void**)&a0,   g_a0);
    cudaGetSymbolAddress((void**)&bb0,  g_bb0);
    cudaGetSymbolAddress((void**)&a1,   g_a1);
    cudaGetSymbolAddress((void**)&bb1,  g_bb1);

    cudaFuncSetAttribute(hmma_gemm_kernel<64, 256, true, true, true, true, 1>,
                         cudaFuncAttributeMaxDynamicSharedMemorySize, 98304);
    cudaFuncSetAttribute(hmma_gemm_kernel<64, 2048, false, false, true, true, 1>,
                         cudaFuncAttributeMaxDynamicSharedMemorySize, 49152);
    cudaFuncSetAttribute(hmma_gemm_kernel<128, 1024, false, false, false, true, 1>,
                         cudaFuncAttributeMaxDynamicSharedMemorySize, 65536);
    cudaFuncSetAttribute(hmma_gemm_kernel<128, 512, false, false, false, false, 0>,
                         cudaFuncAttributeMaxDynamicSharedMemorySize, 65536);

    // lazy aux stream + events (created on the uncaptured correctness call;
    // reused as capture-legal fork/join nodes afterwards)
    static cudaStream_t auxStream = nullptr;
    static cudaEvent_t evFork = nullptr, evHeads = nullptr;
    static int triedInit = 0;
    if (!triedInit) {
        triedInit = 1;
        if (cudaStreamCreateWithFlags(&auxStream, cudaStreamNonBlocking) != cudaSuccess)
            auxStream = nullptr;
        if (auxStream) {
            if (cudaEventCreateWithFlags(&evFork, cudaEventDisableTiming) != cudaSuccess ||
                cudaEventCreateWithFlags(&evHeads, cudaEventDisableTiming) != cudaSuccess)
                auxStream = nullptr;
        }
    }

    if (auxStream) {
        cudaEventRecord(evFork, 0);
        cudaStreamWaitEvent(auxStream, evFork, 0);
        prep_heads_kernel<<<20480, 256, 0, auxStream>>>(HW1, HW2);
        cudaEventRecord(evHeads, auxStream);
    }

    // trunk chain on default stream
    prep_trunk_kernel<<<1160, 256>>>(x, W0, W1,
                                     b0, g0, be0, m0, v0, b1, g1, be1, m1, v1);

    // 1) h = relu(BN(x @ W0 + b0))   3-pass split HMMA -> fp16 (hi only)
    hmma_gemm_kernel<64, 256, true, true, true, true, 1>
        <<<dim3(32, 8, 1), 256, 98304>>>(
        xh, xl, 0LL, w0th, w0tl, 0LL,
        a0, bb0, 0,
        nullptr, hh, nullptr, 0LL, 2048);

    // 2) feats = relu(BN(h @ W1 + b1))  1-pass fp16 -> fp16
    hmma_gemm_kernel<64, 2048, false, false, true, true, 1>
        <<<dim3(16, 8, 1), 256, 49152>>>(
        hh, nullptr, 0LL, w1th, nullptr, 0LL,
        a1, bb1, 0,
        nullptr, fh, nullptr, 0LL, 1024);

    if (auxStream) {
        cudaStreamWaitEvent(0, evHeads, 0);
    } else {
        prep_heads_kernel<<<20480, 256>>>(HW1, HW2);
    }

    // 3) z[n] = relu(feats @ HW1[n] + Hb1[n])  1-pass fp16 -> fp16
    hmma_gemm_kernel<128, 1024, false, false, false, true, 1>
        <<<dim3(4, 8, 128), 256, 65536>>>(
        fh, nullptr, 0LL, hw1t, nullptr, 512LL * 1024,
        nullptr, Hb1, 512,
        nullptr, zh, nullptr, 1024LL * 512, 512);

    // 4) out[:,n,:] = z[n] @ HW2[n] + Hb2[n]  1-pass fp16 -> fp32
    hmma_gemm_kernel<128, 512, false, false, false, false, 0>
        <<<dim3(2, 8, 128), 256, 65536>>>(
        zh, nullptr, 1024LL * 512, hw2t, nullptr, 256LL * 512,
        nullptr, Hb2, 256,
        out, nullptr, nullptr, 256LL, 128 * 256);
}

// round 16
// speedup vs baseline: 1.1228x; 1.0197x over previous
#include <cuda_runtime.h>
#include <cuda_fp16.h>
#include <cstdint>

#define BN_EPS 1e-5f

// ======================= device scratch (no allocs allowed) =================
static __device__ __half g_xh[1024 * 256];                // x fp16, K padded to 256
static __device__ __half g_w0th[2048 * 256];              // W0^T fp16 [2048][256]
static __device__ __half g_hh[1024 * 2048];               // trunk hidden fp16
static __device__ __half g_w1th[1024 * 2048];             // W1^T fp16 [1024][2048]
static __device__ __half g_fh[1024 * 1024];               // feats fp16
static __device__ __half g_hw1t[128u * 512u * 1024u];     // HW1^T [n][512][1024]
static __device__ __half g_hw2t[128u * 256u * 512u];      // HW2^T [n][256][512]
static __device__ __half g_zh[128u * 1024u * 512u];       // z fp16 [n][1024][512]
static __device__ float g_a0[2048], g_bb0[2048];
static __device__ float g_a1[1024], g_bb1[1024];

// ======================= small helpers ======================================
__device__ __forceinline__ uint32_t smem_to_u32(const void* p) {
    uint32_t a;
    asm("{ .reg .u64 t; cvta.to.shared.u64 t, %1; cvt.u32.u64 %0, t; }" : "=r"(a) : "l"(p));
    return a;
}
__device__ __forceinline__ uint32_t swz128(uint32_t off) {
    return off ^ ((off >> 3) & 0x70);
}
__device__ __forceinline__ void cp_async16(uint32_t dst, const void* src) {
    asm volatile("cp.async.cg.shared.global [%0], [%1], 16;" :: "r"(dst), "l"(src));
}
#define CP_COMMIT() asm volatile("cp.async.commit_group;" ::: "memory")
#define CP_WAIT(n)  asm volatile("cp.async.wait_group %0;" :: "n"(n) : "memory")

#define LDMX4(r, addr) \
    asm volatile("ldmatrix.sync.aligned.m8n8.x4.shared.b16 {%0,%1,%2,%3}, [%4];" \
        : "=r"((r)[0]), "=r"((r)[1]), "=r"((r)[2]), "=r"((r)[3]) : "r"(addr))

#define MMA_F16(d, a, b0_, b1_) \
    asm volatile("mma.sync.aligned.m16n8k16.row.col.f32.f16.f16.f32 " \
        "{%0,%1,%2,%3}, {%4,%5,%6,%7}, {%8,%9}, {%0,%1,%2,%3};" \
        : "+f"((d)[0]), "+f"((d)[1]), "+f"((d)[2]), "+f"((d)[3]) \
        : "r"((a)[0]), "r"((a)[1]), "r"((a)[2]), "r"((a)[3]), "r"(b0_), "r"(b1_))

__device__ __forceinline__ uint32_t pack_h2(__half lo16, __half hi16) {
    return ((uint32_t)__half_as_ushort(hi16) << 16) | __half_as_ushort(lo16);
}

// ================= prep: 64x64 transpose (fp16), uint4 stores ===============
__device__ __forceinline__ void tp64(const float* __restrict__ in,
                                     __half* __restrict__ oh,
                                     int R, int C, int Rpad, int r0, int c0,
                                     float* t, int tid) {
#pragma unroll
    for (int k = 0; k < 4; k++) {
        const int u = tid + k * 256;
        const int r = u >> 4;
        const int cq = (u & 15) * 4;
        const int gr = r0 + r;
        float4 v = make_float4(0.f, 0.f, 0.f, 0.f);
        if (gr < R) v = *(const float4*)(in + (long long)gr * C + c0 + cq);
        t[r * 65 + cq]     = v.x;
        t[r * 65 + cq + 1] = v.y;
        t[r * 65 + cq + 2] = v.z;
        t[r * 65 + cq + 3] = v.w;
    }
    __syncthreads();
#pragma unroll
    for (int k = 0; k < 2; k++) {
        const int u = tid + k * 256;
        const int cc = u >> 3;            // output row (source column) 0..63
        const int r8 = (u & 7) * 8;       // 8 consecutive output cols
        uint32_t hp[4];
#pragma unroll
        for (int j = 0; j < 4; j++) {
            const float v0 = t[(r8 + 2 * j) * 65 + cc];
            const float v1 = t[(r8 + 2 * j + 1) * 65 + cc];
            hp[j] = pack_h2(__float2half(v0), __float2half(v1));
        }
        const long long o = (long long)(c0 + cc) * Rpad + r0 + r8;
        *(uint4*)(oh + o) = make_uint4(hp[0], hp[1], hp[2], hp[3]);
    }
}

// ---- trunk prep: bnfold 8 | xconv 512 | W0T 128 | W1T 512  => 1160 blocks --
__global__ __launch_bounds__(256)
void prep_trunk_kernel(const float* __restrict__ x,
                       const float* __restrict__ W0, const float* __restrict__ W1,
                       const float* __restrict__ b0, const float* __restrict__ g0,
                       const float* __restrict__ be0, const float* __restrict__ m0,
                       const float* __restrict__ v0,
                       const float* __restrict__ b1, const float* __restrict__ g1,
                       const float* __restrict__ be1, const float* __restrict__ m1,
                       const float* __restrict__ v1) {
    __shared__ float t[64 * 65];
    const int tid = threadIdx.x;
    const int b = blockIdx.x;

    if (b < 8) {
        const int i = b * 256 + tid;
        if (i < 2048) {
            float a = g0[i] / sqrtf(v0[i] + BN_EPS);
            g_a0[i]  = a;
            g_bb0[i] = be0[i] + (b0[i] - m0[i]) * a;
        }
        if (i < 1024) {
            float a = g1[i] / sqrtf(v1[i] + BN_EPS);
            g_a1[i]  = a;
            g_bb1[i] = be1[i] + (b1[i] - m1[i]) * a;
        }
    } else if (b < 520) {                 // x -> xh [1024][256], 131072 pairs
        const int u = (b - 8) * 256 + tid;            // 0..131071
        const int row = u >> 7;
        const int c2 = (u & 127) * 2;
        float v0 = (c2     < 200) ? x[row * 200 + c2]     : 0.f;
        float v1 = (c2 + 1 < 200) ? x[row * 200 + c2 + 1] : 0.f;
        *(uint32_t*)(g_xh + row * 256 + c2) =
            pack_h2(__float2half(v0), __float2half(v1));
    } else if (b < 648) {                 // W0T: [200][2048]->[2048][256]
        const int i = b - 520;
        const int by = i >> 5, bx = i & 31;
        tp64(W0, g_w0th, 200, 2048, 256, by * 64, bx * 64, t, tid);
    } else {                              // W1T: [2048][1024]->[1024][2048]
        const int i = b - 648;
        const int by = i >> 4, bx = i & 15;
        tp64(W1, g_w1th, 2048, 1024, 2048, by * 64, bx * 64, t, tid);
    }
}

// ---- head prep: HW1T 16384 | HW2T 4096  => 20480 blocks --------------------
__global__ __launch_bounds__(256)
void prep_heads_kernel(const float* __restrict__ HW1, const float* __restrict__ HW2) {
    __shared__ float t[64 * 65];
    const int tid = threadIdx.x;
    const int b = blockIdx.x;
    if (b < 16384) {
        const int head = b >> 7;
        const int rem = b & 127;
        const int by = rem >> 3, bx = rem & 7;
        tp64(HW1 + (long long)head * 1024 * 512,
             g_hw1t + (long long)head * 512 * 1024,
             1024, 512, 1024, by * 64, bx * 64, t, tid);
    } else {
        const int i = b - 16384;
        const int head = i >> 5;
        const int rem = i & 31;
        const int by = rem >> 2, bx = rem & 3;
        tp64(HW2 + (long long)head * 512 * 256,
             g_hw2t + (long long)head * 256 * 512,
             512, 256, 512, by * 64, bx * 64, t, tid);
    }
}

// ============ unified mma.sync GEMM, templated BM/BN/KT =====================
// C = act( A @ B^T * [alpha] + beta ) ; single-pass fp16, fp32 accum.
// BM=128: 256 thr / 8 warps / 2 CTAs/SM (saturated launches — heads).
// BM=64 : 128 thr / 4 warps / 4 CTAs/SM (grid-limited launches — trunk).
// Warp tile 32 x (BN/2). K-chunk 64, 2-stage smem double buffer.
// OUTMODE: 0 = fp32, 1 = fp16.
template <int BM, int BN, int KT, bool HASALPHA, bool RELU, int OUTMODE>
__global__ __launch_bounds__(BM == 64 ? 128 : 256, BM == 64 ? 4 : 2)
void hmma_gemm_kernel(const __half* __restrict__ A, long long sA,
                      const __half* __restrict__ B, long long sB,
                      const float* __restrict__ alpha,
                      const float* __restrict__ bias, int sBias,
                      float* __restrict__ Cf, __half* __restrict__ Ch,
                      long long sC, int ldc) {
    constexpr int NT = BM == 64 ? 128 : 256;  // threads
    constexpr int TA = BM * 128;              // A tile bytes
    constexpr int TB = BN * 128;
    constexpr int OFF_B = TA;
    constexpr int BUF = TA + TB;
    constexpr int NF = BN / 16;               // n8-frags per warp
    constexpr int NG = BN / 32;               // B ldmatrix groups per warp
    constexpr int NCH = KT >> 6;              // K chunks

    extern __shared__ char smem[];
    const uint32_t sb = smem_to_u32(smem);
    const int tid = threadIdx.x;
    const int lane = tid & 31;
    const int w = tid >> 5;
    const int wm = (w >> 1) * 32;
    const int wn = (w & 1) * (BN / 2);
    const int head = blockIdx.z;
    const int mBase = blockIdx.y * BM;
    const int nBase = blockIdx.x * BN;

    const __half* pA = A + (long long)head * sA + (long long)mBase * KT;
    const __half* pB = B + (long long)head * sB + (long long)nBase * KT;

    float acc[2][NF][4];
#pragma unroll
    for (int mi = 0; mi < 2; mi++)
#pragma unroll
        for (int n = 0; n < NF; n++)
#pragma unroll
            for (int q = 0; q < 4; q++) acc[mi][n][q] = 0.0f;

    auto load_chunk = [&](uint32_t buf, int kB) {
#pragma unroll
        for (int u = tid; u < BM * 8; u += NT) {
            const int r = u >> 3, c = u & 7;
            const uint32_t sw = swz128((uint32_t)(r * 128 + c * 16));
            cp_async16(buf + sw, pA + (long long)r * KT + kB + c * 8);
        }
#pragma unroll
        for (int u = tid; u < BN * 8; u += NT) {
            const int r = u >> 3, c = u & 7;
            const uint32_t sw = swz128((uint32_t)(r * 128 + c * 16));
            cp_async16(buf + OFF_B + sw, pB + (long long)r * KT + kB + c * 8);
        }
    };

    load_chunk(sb, 0);
    CP_COMMIT();

    const int aRowA = wm + (lane & 15);
    const int aRowB = wn + (lane & 15);
    const int cSel  = (lane >> 4);

#pragma unroll 1
    for (int c = 0; c < NCH; ++c) {
        if (c + 1 < NCH) {
            load_chunk(sb + ((c + 1) & 1) * BUF, (c + 1) * 64);
            CP_COMMIT();
            CP_WAIT(1);
        } else {
            CP_WAIT(0);
        }
        __syncthreads();

        const uint32_t bA = sb + (c & 1) * BUF;

#pragma unroll
        for (int ks = 0; ks < 4; ks++) {
            const int kc = ks * 2 + cSel;
            uint32_t ah[2][4];
#pragma unroll
            for (int mi = 0; mi < 2; mi++) {
                const uint32_t ad = swz128((uint32_t)((aRowA + mi * 16) * 128 + kc * 16));
                LDMX4(ah[mi], bA + ad);
            }
#pragma unroll
            for (int g = 0; g < NG; g++) {
                uint32_t bh[4];
                const uint32_t bd = swz128((uint32_t)((aRowB + g * 16) * 128 + kc * 16));
                LDMX4(bh, bA + OFF_B + bd);
#pragma unroll
                for (int mi = 0; mi < 2; mi++)
#pragma unroll
                    for (int s = 0; s < 2; s++) {
                        const int n = g * 2 + s;
                        MMA_F16(acc[mi][n], ah[mi], bh[s], bh[s + 2]);
                    }
            }
        }
        __syncthreads();
    }

    // -------------------------------- epilogue ------------------------------
    const float* bp = bias + (long long)head * sBias + nBase;
    const float* ap = HASALPHA ? alpha + nBase : nullptr;
#pragma unroll
    for (int mi = 0; mi < 2; mi++) {
        const int r0 = mBase + wm + mi * 16 + (lane >> 2);
#pragma unroll
        for (int n = 0; n < NF; n++) {
            const int colL = wn + n * 8 + (lane & 3) * 2;
            const float b0 = __ldg(bp + colL);
            const float b1 = __ldg(bp + colL + 1);
            float a0c = 1.0f, a1c = 1.0f;
            if (HASALPHA) { a0c = __ldg(ap + colL); a1c = __ldg(ap + colL + 1); }
#pragma unroll
            for (int rr = 0; rr < 2; rr++) {
                float v0 = HASALPHA ? fmaf(acc[mi][n][rr * 2 + 0], a0c, b0)
                                    : acc[mi][n][rr * 2 + 0] + b0;
                float v1 = HASALPHA ? fmaf(acc[mi][n][rr * 2 + 1], a1c, b1)
                                    : acc[mi][n][rr * 2 + 1] + b1;
                if (RELU) { v0 = fmaxf(v0, 0.0f); v1 = fmaxf(v1, 0.0f); }
                const long long o = (long long)head * sC +
                                    (long long)(r0 + rr * 8) * ldc + nBase + colL;
                if (OUTMODE == 0) {
                    *(float2*)(Cf + o) = make_float2(v0, v1);
                } else {
                    *(uint32_t*)(Ch + o) = pack_h2(__float2half(v0), __float2half(v1));
                }
            }
        }
    }
}

// ================================ launcher ==================================
extern "C" void kernel_launch(void* const* d_in, const int* in_sizes, int n_in,
                              void* d_out, int out_size) {
    const float* x   = (const float*)d_in[0];
    const float* W0  = (const float*)d_in[1];
    const float* b0  = (const float*)d_in[2];
    const float* g0  = (const float*)d_in[3];
    const float* be0 = (const float*)d_in[4];
    const float* m0  = (const float*)d_in[5];
    const float* v0  = (const float*)d_in[6];
    const float* W1  = (const float*)d_in[7];
    const float* b1  = (const float*)d_in[8];
    const float* g1  = (const float*)d_in[9];
    const float* be1 = (const float*)d_in[10];
    const float* m1  = (const float*)d_in[11];
    const float* v1  = (const float*)d_in[12];
    const float* HW1 = (const float*)d_in[13];
    const float* Hb1 = (const float*)d_in[14];
    const float* HW2 = (const float*)d_in[15];
    const float* Hb2 = (const float*)d_in[16];
    float* out = (float*)d_out;

    float *a0, *bb0, *a1, *bb1;
    __half *xh, *w0th, *hh, *w1th, *fh, *hw1t, *hw2t, *zh;
    cudaGetSymbolAddress((void**)&xh,   g_xh);
    cudaGetSymbolAddress((void**)&w0th, g_w0th);
    cudaGetSymbolAddress((void**)&hh,   g_hh);
    cudaGetSymbolAddress((void**)&w1th, g_w1th);
    cudaGetSymbolAddress((void**)&fh,   g_fh);
    cudaGetSymbolAddress((void**)&hw1t, g_hw1t);
    cudaGetSymbolAddress((void**)&hw2t, g_hw2t);
    cudaGetSymbolAddress((void**)&zh,   g_zh);
    cudaGetSymbolAddress((void**)&a0,   g_a0);
    cudaGetSymbolAddress((void**)&bb0,  g_bb0);
    cudaGetSymbolAddress((void**)&a1,   g_a1);
    cudaGetSymbolAddress((void**)&bb1,  g_bb1);

    cudaFuncSetAttribute(hmma_gemm_kernel<64, 64, 256, true, true, 1>,
                         cudaFuncAttributeMaxDynamicSharedMemorySize, 32768);
    cudaFuncSetAttribute(hmma_gemm_kernel<64, 64, 2048, true, true, 1>,
                         cudaFuncAttributeMaxDynamicSharedMemorySize, 32768);
    cudaFuncSetAttribute(hmma_gemm_kernel<128, 128, 1024, false, true, 1>,
                         cudaFuncAttributeMaxDynamicSharedMemorySize, 65536);
    cudaFuncSetAttribute(hmma_gemm_kernel<128, 128, 512, false, false, 0>,
                         cudaFuncAttributeMaxDynamicSharedMemorySize, 65536);

    // lazy aux stream + events (created on the uncaptured correctness call;
    // reused as capture-legal fork/join nodes afterwards)
    static cudaStream_t auxStream = nullptr;
    static cudaEvent_t evFork = nullptr, evHeads = nullptr;
    static int triedInit = 0;
    if (!triedInit) {
        triedInit = 1;
        if (cudaStreamCreateWithFlags(&auxStream, cudaStreamNonBlocking) != cudaSuccess)
            auxStream = nullptr;
        if (auxStream) {
            if (cudaEventCreateWithFlags(&evFork, cudaEventDisableTiming) != cudaSuccess ||
                cudaEventCreateWithFlags(&evHeads, cudaEventDisableTiming) != cudaSuccess)
                auxStream = nullptr;
        }
    }

    if (auxStream) {
        cudaEventRecord(evFork, 0);
        cudaStreamWaitEvent(auxStream, evFork, 0);
        prep_heads_kernel<<<20480, 256, 0, auxStream>>>(HW1, HW2);
        cudaEventRecord(evHeads, auxStream);
    }

    // trunk chain on default stream
    prep_trunk_kernel<<<1160, 256>>>(x, W0, W1,
                                     b0, g0, be0, m0, v0, b1, g1, be1, m1, v1);

    // 1) h = relu(BN(x @ W0 + b0))  1-pass fp16, BM=64 (512 CTAs)
    hmma_gemm_kernel<64, 64, 256, true, true, 1>
        <<<dim3(32, 16, 1), 128, 32768>>>(
        xh, 0LL, w0th, 0LL,
        a0, bb0, 0,
        nullptr, hh, 0LL, 2048);

    // 2) feats = relu(BN(h @ W1 + b1))  1-pass fp16, BM=64 (256 CTAs)
    hmma_gemm_kernel<64, 64, 2048, true, true, 1>
        <<<dim3(16, 16, 1), 128, 32768>>>(
        hh, 0LL, w1th, 0LL,
        a1, bb1, 0,
        nullptr, fh, 0LL, 1024);

    if (auxStream) {
        cudaStreamWaitEvent(0, evHeads, 0);
    } else {
        prep_heads_kernel<<<20480, 256>>>(HW1, HW2);
    }

    // 3) z[n] = relu(feats @ HW1[n] + Hb1[n])  1-pass fp16 (plateau config)
    hmma_gemm_kernel<128, 128, 1024, false, true, 1>
        <<<dim3(4, 8, 128), 256, 65536>>>(
        fh, 0LL, hw1t, 512LL * 1024,
        nullptr, Hb1, 512,
        nullptr, zh, 1024LL * 512, 512);

    // 4) out[:,n,:] = z[n] @ HW2[n] + Hb2[n]  1-pass fp16 -> fp32
    hmma_gemm_kernel<128, 128, 512, false, false, 0>
        <<<dim3(2, 8, 128), 256, 65536>>>(
        zh, 1024LL * 512, hw2t, 256LL * 512,
        nullptr, Hb2, 256,
        out, nullptr, 256LL, 128 * 256);
}